// round 3
// baseline (speedup 1.0000x reference)
#include <cuda_runtime.h>
#include <math.h>

#define F_IN    128
#define HEADS   4
#define CDIM    64
#define HC      256      // HEADS*CDIM
#define HIDDEN  128
#define MAXN    50000
#define MAXG    1000
#define CAP     1024     // per-target edge bin capacity (mean deg ~17)
#define NEG_SLOPE 0.2f
#define TB      8        // targets per block in k_out

// ---------------- scratch (static device globals; no allocation) -------------
__device__ int   g_tgt_of_node[MAXN];
__device__ int   g_need_flag[MAXN];
__device__ int   g_needed_nodes[MAXN];
__device__ int   g_num_needed;
__device__ int   g_tgt_node[MAXG];
__device__ int   g_deg[MAXG];
__device__ int   g_ce_src[MAXG * CAP];
__device__ float g_asrc[MAXN * HEADS];
__device__ float g_adst[MAXN * HEADS];
__device__ float g_wsrc[HEADS][F_IN];     // W_h @ att_src_h
__device__ float g_wdst[HEADS][F_IN];     // W_h @ att_dst_h
__device__ float g_y[MAXG][HEADS][F_IN];  // per-target aggregated x (2 MB)

// ---------------- helpers ----------------
__device__ __forceinline__ void mark_needed(int node) {
    if (atomicCAS(&g_need_flag[node], 0, 1) == 0) {
        int s = atomicAdd(&g_num_needed, 1);
        g_needed_nodes[s] = node;
    }
}

// ---------------- K1: reset scratch ----------------
__global__ void k_init(int N, int G) {
    int i = blockIdx.x * blockDim.x + threadIdx.x;
    if (i < N) { g_tgt_of_node[i] = -1; g_need_flag[i] = 0; }
    if (i < G) g_deg[i] = 0;
    if (i == 0) g_num_needed = 0;
}

// ---------------- K2: mark target nodes ----------------
__global__ void k_targets(const int* __restrict__ ptr,
                          const int* __restrict__ tni, int G) {
    int g = blockIdx.x * blockDim.x + threadIdx.x;
    if (g >= G) return;
    int node = ptr[g] + tni[g];
    g_tgt_of_node[node] = g;
    g_tgt_node[g] = node;
    mark_needed(node);
}

// ---------------- K3: fold attention vectors through W -----------------------
// g_wsrc[h][k] = sum_c W[k, h*64+c] * att_src[h*64+c]   (same for dst)
__global__ void k_prep(const float* __restrict__ W,
                       const float* __restrict__ att_src,
                       const float* __restrict__ att_dst) {
    int tid = threadIdx.x;               // 256
    int k = tid & 127, half = tid >> 7;
    const float* att = half ? att_dst : att_src;
    float* dstp = half ? &g_wdst[0][0] : &g_wsrc[0][0];
    #pragma unroll
    for (int h = 0; h < HEADS; h++) {
        float a = 0.f;
        #pragma unroll 8
        for (int c = 0; c < CDIM; c++)
            a += W[k * HC + h * CDIM + c] * att[h * CDIM + c];
        dstp[h * F_IN + k] = a;
    }
}

// ---------------- K4: edge scan -> bin edges per target, flag sources --------
__global__ void k_edges(const int* __restrict__ ei, int E, int G) {
    int i = blockIdx.x * blockDim.x + threadIdx.x;
    if (i >= E + G) return;
    int src, dst;
    if (i < E) { src = ei[i]; dst = ei[E + i]; }
    else       { src = g_tgt_node[i - E]; dst = src; }   // self loop for target
    int t = g_tgt_of_node[dst];
    if (t < 0) return;
    int pos = atomicAdd(&g_deg[t], 1);
    if (pos < CAP) g_ce_src[t * CAP + pos] = src;
    mark_needed(src);
}

// ---------------- K5: attention logits for needed nodes (1 warp / node) ------
__global__ void k_logits(const float* __restrict__ x) {
    int slot = blockIdx.x * 8 + (threadIdx.x >> 5);
    if (slot >= g_num_needed) return;
    int lane = threadIdx.x & 31;
    int node = g_needed_nodes[slot];
    float4 xv = __ldg((const float4*)(x + (size_t)node * F_IN) + lane);
    float s[HEADS], d[HEADS];
    #pragma unroll
    for (int h = 0; h < HEADS; h++) {
        float4 ws = *((const float4*)&g_wsrc[h][0] + lane);
        float4 wd = *((const float4*)&g_wdst[h][0] + lane);
        s[h] = xv.x * ws.x + xv.y * ws.y + xv.z * ws.z + xv.w * ws.w;
        d[h] = xv.x * wd.x + xv.y * wd.y + xv.z * wd.z + xv.w * wd.w;
    }
    #pragma unroll
    for (int o = 16; o > 0; o >>= 1) {
        #pragma unroll
        for (int h = 0; h < HEADS; h++) {
            s[h] += __shfl_xor_sync(0xFFFFFFFFu, s[h], o);
            d[h] += __shfl_xor_sync(0xFFFFFFFFu, d[h], o);
        }
    }
    if (lane == 0) {
        *(float4*)&g_asrc[node * HEADS] = make_float4(s[0], s[1], s[2], s[3]);
        *(float4*)&g_adst[node * HEADS] = make_float4(d[0], d[1], d[2], d[3]);
    }
}

// ---------------- K6: per-target softmax + raw-x aggregation -----------------
__global__ void k_agg(const float* __restrict__ x) {
    int t = blockIdx.x;
    int tid = threadIdx.x;                       // 256
    __shared__ int   s_src[CAP];
    __shared__ float s_v[CAP][HEADS];
    __shared__ float s_adst[HEADS];
    __shared__ float s_max[HEADS], s_sum[HEADS];

    int deg = min(g_deg[t], CAP);
    int tnode = g_tgt_node[t];
    if (tid < HEADS) s_adst[tid] = g_adst[tnode * HEADS + tid];
    __syncthreads();

    // edge logits with LeakyReLU
    for (int e = tid; e < deg; e += 256) {
        int src = g_ce_src[t * CAP + e];
        s_src[e] = src;
        float4 as = *(const float4*)&g_asrc[src * HEADS];
        float v0 = as.x + s_adst[0], v1 = as.y + s_adst[1];
        float v2 = as.z + s_adst[2], v3 = as.w + s_adst[3];
        s_v[e][0] = (v0 > 0.f) ? v0 : NEG_SLOPE * v0;
        s_v[e][1] = (v1 > 0.f) ? v1 : NEG_SLOPE * v1;
        s_v[e][2] = (v2 > 0.f) ? v2 : NEG_SLOPE * v2;
        s_v[e][3] = (v3 > 0.f) ? v3 : NEG_SLOPE * v3;
    }
    __syncthreads();

    // per-head max + sum (warp h of first 4 warps)
    if (tid < 128) {
        int h = tid >> 5, lane = tid & 31;
        float m = -INFINITY;
        for (int e = lane; e < deg; e += 32) m = fmaxf(m, s_v[e][h]);
        #pragma unroll
        for (int o = 16; o > 0; o >>= 1)
            m = fmaxf(m, __shfl_xor_sync(0xFFFFFFFFu, m, o));
        float sm = 0.f;
        for (int e = lane; e < deg; e += 32) sm += expf(s_v[e][h] - m);
        #pragma unroll
        for (int o = 16; o > 0; o >>= 1)
            sm += __shfl_xor_sync(0xFFFFFFFFu, sm, o);
        if (lane == 0) { s_max[h] = m; s_sum[h] = sm; }
    }
    __syncthreads();

    // alpha in place
    for (int e = tid; e < deg; e += 256) {
        #pragma unroll
        for (int h = 0; h < HEADS; h++)
            s_v[e][h] = expf(s_v[e][h] - s_max[h]) / (s_sum[h] + 1e-16f);
    }
    __syncthreads();

    // y[h][k] = sum_e alpha[e][h] * x[src_e][k]
    int k = tid & 127, hp = tid >> 7;            // hp: heads {0,1} or {2,3}
    int h0 = hp * 2, h1 = h0 + 1;
    float a0 = 0.f, a1 = 0.f;
    int e = 0;
    for (; e + 2 <= deg; e += 2) {
        float xv0 = __ldg(&x[(size_t)s_src[e]     * F_IN + k]);
        float xv1 = __ldg(&x[(size_t)s_src[e + 1] * F_IN + k]);
        a0 += s_v[e][h0] * xv0 + s_v[e + 1][h0] * xv1;
        a1 += s_v[e][h1] * xv0 + s_v[e + 1][h1] * xv1;
    }
    if (e < deg) {
        float xv = __ldg(&x[(size_t)s_src[e] * F_IN + k]);
        a0 += s_v[e][h0] * xv;
        a1 += s_v[e][h1] * xv;
    }
    g_y[t][h0][k] = a0;
    g_y[t][h1][k] = a1;
}

// ---------------- K7: y @ W per head, head mean + bias, FC -------------------
// Block: TB targets, 256 threads. Thread col = tid = h*64+c for stage 1.
__global__ void k_out(const float* __restrict__ W,
                      const float* __restrict__ bias,
                      const float* __restrict__ fcW,
                      const float* __restrict__ fcb,
                      float* __restrict__ out, int G) {
    __shared__ float s_y[TB][HEADS * F_IN];      // 16 KB
    __shared__ float s_part[HEADS][CDIM][TB];    // 8 KB
    __shared__ float s_o[TB][CDIM];              // 2 KB

    int t0 = blockIdx.x * TB;
    int cnt = min(TB, G - t0);
    int tid = threadIdx.x;

    // load y tiles (contiguous across targets)
    const float4* ysrc = (const float4*)&g_y[t0][0][0];
    float4* ydst = (float4*)&s_y[0][0];
    for (int i = tid; i < cnt * (HEADS * F_IN / 4); i += 256)
        ydst[i] = ysrc[i];
    __syncthreads();

    // stage 1: r[t] = y[t,h,:] . W[:, tid]   (tid = h*64+c)
    int h = tid >> 6;
    float r[TB];
    #pragma unroll
    for (int t = 0; t < TB; t++) r[t] = 0.f;
    const float4* sy4 = (const float4*)&s_y[0][0];
    #pragma unroll 4
    for (int k4 = 0; k4 < 32; k4++) {
        float w0 = W[(k4 * 4 + 0) * HC + tid];
        float w1 = W[(k4 * 4 + 1) * HC + tid];
        float w2 = W[(k4 * 4 + 2) * HC + tid];
        float w3 = W[(k4 * 4 + 3) * HC + tid];
        #pragma unroll
        for (int t = 0; t < TB; t++) {
            float4 yv = sy4[t * 128 + h * 32 + k4];
            r[t] += yv.x * w0 + yv.y * w1 + yv.z * w2 + yv.w * w3;
        }
    }
    {
        int c = tid & 63;
        #pragma unroll
        for (int t = 0; t < TB; t++) s_part[h][c][t] = r[t];
    }
    __syncthreads();

    // stage 2: head mean + bias
    for (int idx = tid; idx < cnt * CDIM; idx += 256) {
        int t = idx >> 6, c = idx & 63;
        float o = (s_part[0][c][t] + s_part[1][c][t] +
                   s_part[2][c][t] + s_part[3][c][t]) * 0.25f + bias[c];
        s_o[t][c] = o;
    }
    __syncthreads();

    // stage 3: FC  out[t] = s_o[t] @ fcW + fcb
    int j = tid & 127, tg = tid >> 7;
    for (int t = tg; t < cnt; t += 2) {
        float rr = fcb[j];
        #pragma unroll 8
        for (int c = 0; c < CDIM; c++)
            rr += s_o[t][c] * fcW[c * HIDDEN + j];
        out[(size_t)(t0 + t) * HIDDEN + j] = rr;
    }
}

// ---------------- launch ----------------
extern "C" void kernel_launch(void* const* d_in, const int* in_sizes, int n_in,
                              void* d_out, int out_size) {
    const float* x        = (const float*)d_in[0];
    const float* W        = (const float*)d_in[1];
    const float* att_src  = (const float*)d_in[2];
    const float* att_dst  = (const float*)d_in[3];
    const float* bias     = (const float*)d_in[4];
    const float* fc_W     = (const float*)d_in[5];
    const float* fc_b     = (const float*)d_in[6];
    const int*   ei       = (const int*)d_in[7];
    const int*   ptr      = (const int*)d_in[8];
    const int*   tni      = (const int*)d_in[9];
    float*       out      = (float*)d_out;

    int N = in_sizes[0] / F_IN;        // 50000
    int E = in_sizes[7] / 2;           // 800000
    int G = in_sizes[9];               // 1000

    k_init<<<(N + 255) / 256, 256>>>(N, G);
    k_targets<<<(G + 255) / 256, 256>>>(ptr, tni, G);
    k_prep<<<1, 256>>>(W, att_src, att_dst);
    k_edges<<<(E + G + 255) / 256, 256>>>(ei, E, G);
    k_logits<<<(MAXN + 7) / 8, 256>>>(x);
    k_agg<<<G, 256>>>(x);
    k_out<<<(G + TB - 1) / TB, 256>>>(W, bias, fc_W, fc_b, out, G);
}

// round 4
// speedup vs baseline: 1.1692x; 1.1692x over previous
#include <cuda_runtime.h>
#include <math.h>

#define F_IN    128
#define HEADS   4
#define CDIM    64
#define HC      256      // HEADS*CDIM
#define HIDDEN  128
#define MAXG    1000
#define CAP     256      // per-target edge bin capacity (mean deg ~17, Poisson)
#define NEG_SLOPE 0.2f
#define TB      8        // targets per block in k_out

// ---------------- scratch (static device globals; no allocation) -------------
__device__ int   g_tgt_node[MAXG];
__device__ int   g_deg[MAXG];
__device__ int   g_ce_src[MAXG * CAP];    // 1 MB
__device__ float g_wsrc[HEADS][F_IN];     // W_h @ att_src_h
__device__ float g_wdst[HEADS][F_IN];     // W_h @ att_dst_h
__device__ float g_y[MAXG][HEADS][F_IN];  // per-target aggregated x (2 MB)

// ---------------- K1: setup (prep + targets + deg zero), one launch ----------
__global__ void k_setup(const float* __restrict__ W,
                        const float* __restrict__ att_src,
                        const float* __restrict__ att_dst,
                        const int* __restrict__ ptr,
                        const int* __restrict__ tni, int G) {
    int tid = threadIdx.x;
    if (blockIdx.x == 0) {
        // fold attention vectors through W:
        // g_wsrc[h][k] = sum_c W[k, h*64+c] * att_src[h*64+c]
        int k = tid & 127, half = tid >> 7;
        const float* att = half ? att_dst : att_src;
        float* dstp = half ? &g_wdst[0][0] : &g_wsrc[0][0];
        #pragma unroll
        for (int h = 0; h < HEADS; h++) {
            float a = 0.f;
            #pragma unroll 8
            for (int c = 0; c < CDIM; c++)
                a += W[k * HC + h * CDIM + c] * att[h * CDIM + c];
            dstp[h * F_IN + k] = a;
        }
    } else {
        int g = (blockIdx.x - 1) * 256 + tid;
        if (g < G) {
            g_deg[g] = 0;
            g_tgt_node[g] = ptr[g] + tni[g];
        }
    }
}

// ---------------- K2: edge scan, table-free dst->target test ------------------
// Items: [0, E/4) -> 4 packed edges each; [E/4, E/4+G) -> one self loop each.
__global__ void k_edges(const int* __restrict__ ei,
                        const int* __restrict__ ptr,
                        const int* __restrict__ tni,
                        int E, int G) {
    int nE4 = E >> 2;
    int item = blockIdx.x * blockDim.x + threadIdx.x;
    if (item < nE4) {
        int4 s4 = __ldg((const int4*)ei + item);
        int4 d4 = __ldg((const int4*)(ei + E) + item);
        int p0 = __ldg(&ptr[0]);
        int stride = __ldg(&ptr[1]) - p0;
        #pragma unroll
        for (int q = 0; q < 4; q++) {
            int src = (q == 0) ? s4.x : (q == 1) ? s4.y : (q == 2) ? s4.z : s4.w;
            int dst = (q == 0) ? d4.x : (q == 1) ? d4.y : (q == 2) ? d4.z : d4.w;
            // locate graph g with ptr[g] <= dst < ptr[g+1]
            int g = -1;
            if (stride > 0) {
                int gg = (dst - p0) / stride;
                if (gg >= 0 && gg < G &&
                    __ldg(&ptr[gg]) <= dst && dst < __ldg(&ptr[gg + 1]))
                    g = gg;
            }
            if (g < 0) {  // non-uniform ptr fallback: binary search
                int lo = 0, hi = G;
                if (dst >= p0 && dst < __ldg(&ptr[G])) {
                    while (hi - lo > 1) {
                        int mid = (lo + hi) >> 1;
                        if (__ldg(&ptr[mid]) <= dst) lo = mid; else hi = mid;
                    }
                    g = lo;
                }
            }
            if (g >= 0 && __ldg(&ptr[g]) + __ldg(&tni[g]) == dst) {
                int pos = atomicAdd(&g_deg[g], 1);
                if (pos < CAP) g_ce_src[g * CAP + pos] = src;
            }
        }
    } else if (item - nE4 < G) {
        int g = item - nE4;                 // self loop of the target node
        int node = g_tgt_node[g];
        int pos = atomicAdd(&g_deg[g], 1);
        if (pos < CAP) g_ce_src[g * CAP + pos] = node;
    }
}

// ---------------- K3: fused logits + softmax + raw-x aggregation -------------
__global__ __launch_bounds__(256)
void k_agg(const float* __restrict__ x) {
    int t = blockIdx.x;
    int tid = threadIdx.x;                       // 256 = 8 warps
    int w = tid >> 5, lane = tid & 31;
    __shared__ int   s_src[CAP];
    __shared__ float s_v[CAP][HEADS];            // a_src, then alpha
    __shared__ __align__(16) float s_adst[HEADS];
    __shared__ float s_max[HEADS], s_sum[HEADS];

    int deg = min(g_deg[t], CAP);
    int tnode = g_tgt_node[t];

    for (int e = tid; e < deg; e += 256)
        s_src[e] = g_ce_src[t * CAP + e];
    __syncthreads();

    // warp 0: target's a_dst; all warps: per-edge a_src (warp-per-edge)
    if (w == 0) {
        float4 xv = __ldg((const float4*)(x + (size_t)tnode * F_IN) + lane);
        float d[HEADS];
        #pragma unroll
        for (int h = 0; h < HEADS; h++) {
            float4 wd = *((const float4*)&g_wdst[h][0] + lane);
            d[h] = xv.x * wd.x + xv.y * wd.y + xv.z * wd.z + xv.w * wd.w;
        }
        #pragma unroll
        for (int o = 16; o > 0; o >>= 1)
            #pragma unroll
            for (int h = 0; h < HEADS; h++)
                d[h] += __shfl_xor_sync(0xFFFFFFFFu, d[h], o);
        if (lane == 0)
            *(float4*)s_adst = make_float4(d[0], d[1], d[2], d[3]);
    }
    for (int e = w; e < deg; e += 8) {
        int src = s_src[e];
        float4 xv = __ldg((const float4*)(x + (size_t)src * F_IN) + lane);
        float s[HEADS];
        #pragma unroll
        for (int h = 0; h < HEADS; h++) {
            float4 ws = *((const float4*)&g_wsrc[h][0] + lane);
            s[h] = xv.x * ws.x + xv.y * ws.y + xv.z * ws.z + xv.w * ws.w;
        }
        #pragma unroll
        for (int o = 16; o > 0; o >>= 1)
            #pragma unroll
            for (int h = 0; h < HEADS; h++)
                s[h] += __shfl_xor_sync(0xFFFFFFFFu, s[h], o);
        if (lane == 0)
            *(float4*)&s_v[e][0] = make_float4(s[0], s[1], s[2], s[3]);
    }
    __syncthreads();

    // per-head max + sum of exp (one warp per head), leaky applied on the fly
    if (tid < 128) {
        int h = tid >> 5, l = tid & 31;
        float ad = s_adst[h];
        float m = -INFINITY;
        for (int e = l; e < deg; e += 32) {
            float v = s_v[e][h] + ad;
            v = (v > 0.f) ? v : NEG_SLOPE * v;
            m = fmaxf(m, v);
        }
        #pragma unroll
        for (int o = 16; o > 0; o >>= 1)
            m = fmaxf(m, __shfl_xor_sync(0xFFFFFFFFu, m, o));
        float sm = 0.f;
        for (int e = l; e < deg; e += 32) {
            float v = s_v[e][h] + ad;
            v = (v > 0.f) ? v : NEG_SLOPE * v;
            sm += expf(v - m);
        }
        #pragma unroll
        for (int o = 16; o > 0; o >>= 1)
            sm += __shfl_xor_sync(0xFFFFFFFFu, sm, o);
        if (l == 0) { s_max[h] = m; s_sum[h] = sm; }
    }
    __syncthreads();

    // alpha in place
    for (int e = tid; e < deg; e += 256) {
        #pragma unroll
        for (int h = 0; h < HEADS; h++) {
            float v = s_v[e][h] + s_adst[h];
            v = (v > 0.f) ? v : NEG_SLOPE * v;
            s_v[e][h] = expf(v - s_max[h]) / (s_sum[h] + 1e-16f);
        }
    }
    __syncthreads();

    // y[h][k] = sum_e alpha[e][h] * x[src_e][k]   (rows now L2-hot)
    int k = tid & 127, hp = tid >> 7;            // hp: heads {0,1} or {2,3}
    int h0 = hp * 2, h1 = h0 + 1;
    float a0 = 0.f, a1 = 0.f;
    int e = 0;
    for (; e + 2 <= deg; e += 2) {
        float xv0 = __ldg(&x[(size_t)s_src[e]     * F_IN + k]);
        float xv1 = __ldg(&x[(size_t)s_src[e + 1] * F_IN + k]);
        a0 += s_v[e][h0] * xv0 + s_v[e + 1][h0] * xv1;
        a1 += s_v[e][h1] * xv0 + s_v[e + 1][h1] * xv1;
    }
    if (e < deg) {
        float xv = __ldg(&x[(size_t)s_src[e] * F_IN + k]);
        a0 += s_v[e][h0] * xv;
        a1 += s_v[e][h1] * xv;
    }
    g_y[t][h0][k] = a0;
    g_y[t][h1][k] = a1;
}

// ---------------- K4: y @ W per head, head mean + bias, FC -------------------
__global__ void k_out(const float* __restrict__ W,
                      const float* __restrict__ bias,
                      const float* __restrict__ fcW,
                      const float* __restrict__ fcb,
                      float* __restrict__ out, int G) {
    __shared__ float s_y[TB][HEADS * F_IN];      // 16 KB
    __shared__ float s_part[HEADS][CDIM][TB];    // 8 KB
    __shared__ float s_o[TB][CDIM];              // 2 KB

    int t0 = blockIdx.x * TB;
    int cnt = min(TB, G - t0);
    int tid = threadIdx.x;

    const float4* ysrc = (const float4*)&g_y[t0][0][0];
    float4* ydst = (float4*)&s_y[0][0];
    for (int i = tid; i < cnt * (HEADS * F_IN / 4); i += 256)
        ydst[i] = ysrc[i];
    __syncthreads();

    // stage 1: r[t] = y[t,h,:] . W[:, tid]   (tid = h*64+c)
    int h = tid >> 6;
    float r[TB];
    #pragma unroll
    for (int t = 0; t < TB; t++) r[t] = 0.f;
    const float4* sy4 = (const float4*)&s_y[0][0];
    #pragma unroll 4
    for (int k4 = 0; k4 < 32; k4++) {
        float w0 = W[(k4 * 4 + 0) * HC + tid];
        float w1 = W[(k4 * 4 + 1) * HC + tid];
        float w2 = W[(k4 * 4 + 2) * HC + tid];
        float w3 = W[(k4 * 4 + 3) * HC + tid];
        #pragma unroll
        for (int t = 0; t < TB; t++) {
            float4 yv = sy4[t * 128 + h * 32 + k4];
            r[t] += yv.x * w0 + yv.y * w1 + yv.z * w2 + yv.w * w3;
        }
    }
    {
        int c = tid & 63;
        #pragma unroll
        for (int t = 0; t < TB; t++) s_part[h][c][t] = r[t];
    }
    __syncthreads();

    // stage 2: head mean + bias
    for (int idx = tid; idx < cnt * CDIM; idx += 256) {
        int t = idx >> 6, c = idx & 63;
        float o = (s_part[0][c][t] + s_part[1][c][t] +
                   s_part[2][c][t] + s_part[3][c][t]) * 0.25f + bias[c];
        s_o[t][c] = o;
    }
    __syncthreads();

    // stage 3: FC  out[t] = s_o[t] @ fcW + fcb
    int j = tid & 127, tg = tid >> 7;
    for (int t = tg; t < cnt; t += 2) {
        float rr = fcb[j];
        #pragma unroll 8
        for (int c = 0; c < CDIM; c++)
            rr += s_o[t][c] * fcW[c * HIDDEN + j];
        out[(size_t)(t0 + t) * HIDDEN + j] = rr;
    }
}

// ---------------- launch ----------------
extern "C" void kernel_launch(void* const* d_in, const int* in_sizes, int n_in,
                              void* d_out, int out_size) {
    const float* x        = (const float*)d_in[0];
    const float* W        = (const float*)d_in[1];
    const float* att_src  = (const float*)d_in[2];
    const float* att_dst  = (const float*)d_in[3];
    const float* bias     = (const float*)d_in[4];
    const float* fc_W     = (const float*)d_in[5];
    const float* fc_b     = (const float*)d_in[6];
    const int*   ei       = (const int*)d_in[7];
    const int*   ptr      = (const int*)d_in[8];
    const int*   tni      = (const int*)d_in[9];
    float*       out      = (float*)d_out;

    int E = in_sizes[7] / 2;           // 800000
    int G = in_sizes[9];               // 1000

    k_setup<<<1 + (G + 255) / 256, 256>>>(W, att_src, att_dst, ptr, tni, G);
    int items = (E >> 2) + G;
    k_edges<<<(items + 255) / 256, 256>>>(ei, ptr, tni, E, G);
    k_agg<<<G, 256>>>(x);
    k_out<<<(G + TB - 1) / TB, 256>>>(W, bias, fc_W, fc_b, out, G);
}

// round 5
// speedup vs baseline: 1.2030x; 1.0289x over previous
#include <cuda_runtime.h>
#include <math.h>

#define F_IN    128
#define HEADS   4
#define CDIM    64
#define HC      256      // HEADS*CDIM
#define HIDDEN  128
#define YDIM    512      // HEADS*F_IN
#define MAXG    1000
#define CAP     256      // per-target edge bin capacity (mean deg ~17, Poisson)
#define NEG_SLOPE 0.2f
#define TB      8        // targets per block in k_out2

// ---------------- scratch (static device globals; no allocation) -------------
__device__ int   g_tgt_node[MAXG];
__device__ int   g_deg[MAXG];
__device__ int   g_ce_src[MAXG * CAP];    // 1 MB
__device__ float g_wsrc[HEADS][F_IN];     // W_h @ att_src_h
__device__ float g_wdst[HEADS][F_IN];     // W_h @ att_dst_h
__device__ float g_y[MAXG][HEADS][F_IN];  // per-target aggregated x (2 MB)
__device__ float g_M[YDIM][HIDDEN];       // 0.25 * (W_h @ fcW), stacked (256 KB)
__device__ float g_b2[HIDDEN];            // bias @ fcW + fcb

// ---------------- K1: setup (att-fold + targets + deg zero) ------------------
__global__ void k_setup(const float* __restrict__ W,
                        const float* __restrict__ att_src,
                        const float* __restrict__ att_dst,
                        const int* __restrict__ ptr,
                        const int* __restrict__ tni, int G) {
    int tid = threadIdx.x;
    if (blockIdx.x == 0) {
        // g_wsrc[h][k] = sum_c W[k, h*64+c] * att_src[h*64+c]
        int k = tid & 127, half = tid >> 7;
        const float* att = half ? att_dst : att_src;
        float* dstp = half ? &g_wdst[0][0] : &g_wsrc[0][0];
        #pragma unroll
        for (int h = 0; h < HEADS; h++) {
            float a = 0.f;
            #pragma unroll 8
            for (int c = 0; c < CDIM; c++)
                a += W[k * HC + h * CDIM + c] * att[h * CDIM + c];
            dstp[h * F_IN + k] = a;
        }
    } else {
        int g = (blockIdx.x - 1) * 256 + tid;
        if (g < G) {
            g_deg[g] = 0;
            g_tgt_node[g] = ptr[g] + tni[g];
        }
    }
}

// ---------------- K1b: fold fcW through W -> M, and b2 -----------------------
// grid 256 blocks x 256 threads: hk = bid*2 + (tid>>7), j = tid&127
__global__ void k_setupM(const float* __restrict__ W,
                         const float* __restrict__ fcW,
                         const float* __restrict__ bias,
                         const float* __restrict__ fcb) {
    int tid = threadIdx.x;
    int hk = blockIdx.x * 2 + (tid >> 7);
    int j = tid & 127;
    int h = hk >> 7, k = hk & 127;
    const float* wrow = W + k * HC + h * CDIM;
    float acc = 0.f;
    #pragma unroll 8
    for (int c = 0; c < CDIM; c++)
        acc += __ldg(&wrow[c]) * __ldg(&fcW[c * HIDDEN + j]);
    g_M[hk][j] = 0.25f * acc;
    if (blockIdx.x == 0 && tid < HIDDEN) {
        float b = fcb[tid];
        #pragma unroll 8
        for (int c = 0; c < CDIM; c++)
            b += bias[c] * fcW[c * HIDDEN + tid];
        g_b2[tid] = b;
    }
}

// ---------------- K2: edge scan, table-free dst->target test ------------------
__global__ void k_edges(const int* __restrict__ ei,
                        const int* __restrict__ ptr,
                        const int* __restrict__ tni,
                        int E, int G) {
    int nE4 = E >> 2;
    int item = blockIdx.x * blockDim.x + threadIdx.x;
    if (item < nE4) {
        int4 s4 = __ldg((const int4*)ei + item);
        int4 d4 = __ldg((const int4*)(ei + E) + item);
        int p0 = __ldg(&ptr[0]);
        int stride = __ldg(&ptr[1]) - p0;
        #pragma unroll
        for (int q = 0; q < 4; q++) {
            int src = (q == 0) ? s4.x : (q == 1) ? s4.y : (q == 2) ? s4.z : s4.w;
            int dst = (q == 0) ? d4.x : (q == 1) ? d4.y : (q == 2) ? d4.z : d4.w;
            int g = -1;
            if (stride > 0) {
                int gg = (dst - p0) / stride;
                if (gg >= 0 && gg < G &&
                    __ldg(&ptr[gg]) <= dst && dst < __ldg(&ptr[gg + 1]))
                    g = gg;
            }
            if (g < 0) {  // non-uniform ptr fallback: binary search
                int lo = 0, hi = G;
                if (dst >= p0 && dst < __ldg(&ptr[G])) {
                    while (hi - lo > 1) {
                        int mid = (lo + hi) >> 1;
                        if (__ldg(&ptr[mid]) <= dst) lo = mid; else hi = mid;
                    }
                    g = lo;
                }
            }
            if (g >= 0 && __ldg(&ptr[g]) + __ldg(&tni[g]) == dst) {
                int pos = atomicAdd(&g_deg[g], 1);
                if (pos < CAP) g_ce_src[g * CAP + pos] = src;
            }
        }
    } else if (item - nE4 < G) {
        int g = item - nE4;                 // self loop of the target node
        int node = g_tgt_node[g];
        int pos = atomicAdd(&g_deg[g], 1);
        if (pos < CAP) g_ce_src[g * CAP + pos] = node;
    }
}

// ---------------- K3: fused logits + softmax + raw-x aggregation -------------
__global__ __launch_bounds__(256)
void k_agg(const float* __restrict__ x) {
    int t = blockIdx.x;
    int tid = threadIdx.x;                       // 256 = 8 warps
    int w = tid >> 5, lane = tid & 31;
    __shared__ int   s_src[CAP];
    __shared__ float s_v[CAP][HEADS];            // a_src, then alpha
    __shared__ __align__(16) float s_adst[HEADS];
    __shared__ float s_max[HEADS], s_sum[HEADS];

    int deg = min(g_deg[t], CAP);
    int tnode = g_tgt_node[t];

    for (int e = tid; e < deg; e += 256)
        s_src[e] = g_ce_src[t * CAP + e];
    __syncthreads();

    // warp 0: target's a_dst; all warps: per-edge a_src (warp-per-edge)
    if (w == 0) {
        float4 xv = __ldg((const float4*)(x + (size_t)tnode * F_IN) + lane);
        float d[HEADS];
        #pragma unroll
        for (int h = 0; h < HEADS; h++) {
            float4 wd = *((const float4*)&g_wdst[h][0] + lane);
            d[h] = xv.x * wd.x + xv.y * wd.y + xv.z * wd.z + xv.w * wd.w;
        }
        #pragma unroll
        for (int o = 16; o > 0; o >>= 1)
            #pragma unroll
            for (int h = 0; h < HEADS; h++)
                d[h] += __shfl_xor_sync(0xFFFFFFFFu, d[h], o);
        if (lane == 0)
            *(float4*)s_adst = make_float4(d[0], d[1], d[2], d[3]);
    }
    for (int e = w; e < deg; e += 8) {
        int src = s_src[e];
        float4 xv = __ldg((const float4*)(x + (size_t)src * F_IN) + lane);
        float s[HEADS];
        #pragma unroll
        for (int h = 0; h < HEADS; h++) {
            float4 ws = *((const float4*)&g_wsrc[h][0] + lane);
            s[h] = xv.x * ws.x + xv.y * ws.y + xv.z * ws.z + xv.w * ws.w;
        }
        #pragma unroll
        for (int o = 16; o > 0; o >>= 1)
            #pragma unroll
            for (int h = 0; h < HEADS; h++)
                s[h] += __shfl_xor_sync(0xFFFFFFFFu, s[h], o);
        if (lane == 0)
            *(float4*)&s_v[e][0] = make_float4(s[0], s[1], s[2], s[3]);
    }
    __syncthreads();

    // per-head max + sum of exp (one warp per head)
    if (tid < 128) {
        int h = tid >> 5, l = tid & 31;
        float ad = s_adst[h];
        float m = -INFINITY;
        for (int e = l; e < deg; e += 32) {
            float v = s_v[e][h] + ad;
            v = (v > 0.f) ? v : NEG_SLOPE * v;
            m = fmaxf(m, v);
        }
        #pragma unroll
        for (int o = 16; o > 0; o >>= 1)
            m = fmaxf(m, __shfl_xor_sync(0xFFFFFFFFu, m, o));
        float sm = 0.f;
        for (int e = l; e < deg; e += 32) {
            float v = s_v[e][h] + ad;
            v = (v > 0.f) ? v : NEG_SLOPE * v;
            sm += expf(v - m);
        }
        #pragma unroll
        for (int o = 16; o > 0; o >>= 1)
            sm += __shfl_xor_sync(0xFFFFFFFFu, sm, o);
        if (l == 0) { s_max[h] = m; s_sum[h] = sm; }
    }
    __syncthreads();

    // alpha in place
    for (int e = tid; e < deg; e += 256) {
        #pragma unroll
        for (int h = 0; h < HEADS; h++) {
            float v = s_v[e][h] + s_adst[h];
            v = (v > 0.f) ? v : NEG_SLOPE * v;
            s_v[e][h] = expf(v - s_max[h]) / (s_sum[h] + 1e-16f);
        }
    }
    __syncthreads();

    // y[h][k] = sum_e alpha[e][h] * x[src_e][k]   (rows L2-hot from pass 1)
    int k = tid & 127, hp = tid >> 7;            // hp: heads {0,1} or {2,3}
    int h0 = hp * 2, h1 = h0 + 1;
    float a0 = 0.f, a1 = 0.f;
    int e = 0;
    for (; e + 2 <= deg; e += 2) {
        float xv0 = __ldg(&x[(size_t)s_src[e]     * F_IN + k]);
        float xv1 = __ldg(&x[(size_t)s_src[e + 1] * F_IN + k]);
        a0 += s_v[e][h0] * xv0 + s_v[e + 1][h0] * xv1;
        a1 += s_v[e][h1] * xv0 + s_v[e + 1][h1] * xv1;
    }
    if (e < deg) {
        float xv = __ldg(&x[(size_t)s_src[e] * F_IN + k]);
        a0 += s_v[e][h0] * xv;
        a1 += s_v[e][h1] * xv;
    }
    g_y[t][h0][k] = a0;
    g_y[t][h1][k] = a1;
}

// ---------------- K4: out = Y @ M + b2  (Y row = 512 = HEADS*F_IN) -----------
// grid = 2 * ceil(G/TB); blockIdx&1 selects 64-col half. 256 threads:
// jloc = tid&63 (column), ksub = tid>>6 (k-quarter of 128).
__global__ __launch_bounds__(256, 2)
void k_out2(float* __restrict__ out, int G) {
    __shared__ __align__(16) float s_y[TB][YDIM];     // 16 KB
    __shared__ float s_part[4][TB][64];               // 8 KB

    int bc = blockIdx.x & 1;
    int t0 = (blockIdx.x >> 1) * TB;
    if (t0 >= G) return;
    int cnt = min(TB, G - t0);
    int tid = threadIdx.x;

    const float4* ysrc = (const float4*)&g_y[t0][0][0];
    float4* ydst = (float4*)&s_y[0][0];
    for (int i = tid; i < cnt * (YDIM / 4); i += 256)
        ydst[i] = ysrc[i];
    __syncthreads();

    int jloc = tid & 63, ksub = tid >> 6;
    int j = bc * 64 + jloc;
    int k0 = ksub * 128;

    float r[TB];
    #pragma unroll
    for (int t = 0; t < TB; t++) r[t] = 0.f;

    #pragma unroll 4
    for (int kk = 0; kk < 128; kk += 4) {
        int k = k0 + kk;
        float m0 = __ldg(&g_M[k + 0][j]);
        float m1 = __ldg(&g_M[k + 1][j]);
        float m2 = __ldg(&g_M[k + 2][j]);
        float m3 = __ldg(&g_M[k + 3][j]);
        #pragma unroll
        for (int t = 0; t < TB; t++) {
            float4 yv = *(const float4*)&s_y[t][k];
            r[t] += yv.x * m0 + yv.y * m1 + yv.z * m2 + yv.w * m3;
        }
    }
    #pragma unroll
    for (int t = 0; t < TB; t++) s_part[ksub][t][jloc] = r[t];
    __syncthreads();

    for (int idx = tid; idx < cnt * 64; idx += 256) {
        int t = idx >> 6, jl = idx & 63;
        float v = s_part[0][t][jl] + s_part[1][t][jl] +
                  s_part[2][t][jl] + s_part[3][t][jl];
        out[(size_t)(t0 + t) * HIDDEN + bc * 64 + jl] = v + g_b2[bc * 64 + jl];
    }
}

// ---------------- launch ----------------
extern "C" void kernel_launch(void* const* d_in, const int* in_sizes, int n_in,
                              void* d_out, int out_size) {
    const float* x        = (const float*)d_in[0];
    const float* W        = (const float*)d_in[1];
    const float* att_src  = (const float*)d_in[2];
    const float* att_dst  = (const float*)d_in[3];
    const float* bias     = (const float*)d_in[4];
    const float* fc_W     = (const float*)d_in[5];
    const float* fc_b     = (const float*)d_in[6];
    const int*   ei       = (const int*)d_in[7];
    const int*   ptr      = (const int*)d_in[8];
    const int*   tni      = (const int*)d_in[9];
    float*       out      = (float*)d_out;

    int E = in_sizes[7] / 2;           // 800000
    int G = in_sizes[9];               // 1000

    k_setup<<<1 + (G + 255) / 256, 256>>>(W, att_src, att_dst, ptr, tni, G);
    k_setupM<<<YDIM / 2, 256>>>(W, fc_W, bias, fc_b);
    int items = (E >> 2) + G;
    k_edges<<<(items + 255) / 256, 256>>>(ei, ptr, tni, E, G);
    k_agg<<<G, 256>>>(x);
    k_out2<<<2 * ((G + TB - 1) / TB), 256>>>(out, G);
}

// round 6
// speedup vs baseline: 1.2776x; 1.0620x over previous
#include <cuda_runtime.h>
#include <math.h>

#define F_IN    128
#define HEADS   4
#define CDIM    64
#define HC      256      // HEADS*CDIM
#define HIDDEN  128
#define YDIM    512      // HEADS*F_IN
#define MAXG    1000
#define CAP     256      // per-target edge bin capacity
#define XCAP    64       // rows cached in smem (deg ~Poisson(17), max ~40)
#define NEG_SLOPE 0.2f
#define TB      16       // targets per block in k_out2

// ---------------- scratch (static device globals; no allocation) -------------
__device__ int   g_tgt_node[MAXG];
__device__ int   g_deg[MAXG];
__device__ int   g_ce_src[MAXG * CAP];    // 1 MB
__device__ float g_wsrc[HEADS][F_IN];     // W_h @ att_src_h
__device__ float g_wdst[HEADS][F_IN];     // W_h @ att_dst_h
__device__ float g_y[MAXG][HEADS][F_IN];  // per-target aggregated x (2 MB)
__device__ float g_M[YDIM][HIDDEN];       // 0.25 * (W_h @ fcW), stacked (256 KB)
__device__ float g_b2[HIDDEN];            // bias @ fcW + fcb

// ---------------- K1: all setup in one launch --------------------------------
// blocks: [0] att-fold | [1, 1+TGB) targets+deg | [1+TGB, 1+TGB+256) M-fold
//         | [1+TGB+256] b2
__global__ void k_setup(const float* __restrict__ W,
                        const float* __restrict__ att_src,
                        const float* __restrict__ att_dst,
                        const float* __restrict__ fcW,
                        const float* __restrict__ bias,
                        const float* __restrict__ fcb,
                        const int* __restrict__ ptr,
                        const int* __restrict__ tni, int G, int TGB) {
    int bid = blockIdx.x, tid = threadIdx.x;
    if (bid == 0) {
        // g_wsrc[h][k] = sum_c W[k, h*64+c] * att_src[h*64+c]
        int k = tid & 127, half = tid >> 7;
        const float* att = half ? att_dst : att_src;
        float* dstp = half ? &g_wdst[0][0] : &g_wsrc[0][0];
        #pragma unroll
        for (int h = 0; h < HEADS; h++) {
            float a = 0.f;
            #pragma unroll 8
            for (int c = 0; c < CDIM; c++)
                a += W[k * HC + h * CDIM + c] * att[h * CDIM + c];
            dstp[h * F_IN + k] = a;
        }
    } else if (bid <= TGB) {
        int g = (bid - 1) * 256 + tid;
        if (g < G) {
            g_deg[g] = 0;
            g_tgt_node[g] = ptr[g] + tni[g];
        }
    } else if (bid <= TGB + 256) {
        // M[h*128+k][j] = 0.25 * sum_c W[k, h*64+c] * fcW[c*128+j]
        int hk = (bid - 1 - TGB) * 2 + (tid >> 7);
        int j = tid & 127;
        int h = hk >> 7, k = hk & 127;
        const float* wrow = W + k * HC + h * CDIM;
        float acc = 0.f;
        #pragma unroll 8
        for (int c = 0; c < CDIM; c++)
            acc += __ldg(&wrow[c]) * __ldg(&fcW[c * HIDDEN + j]);
        g_M[hk][j] = 0.25f * acc;
    } else {
        if (tid < HIDDEN) {
            float b = fcb[tid];
            #pragma unroll 8
            for (int c = 0; c < CDIM; c++)
                b += bias[c] * fcW[c * HIDDEN + tid];
            g_b2[tid] = b;
        }
    }
}

// ---------------- K2: edge scan, table-free dst->target test ------------------
__global__ void k_edges(const int* __restrict__ ei,
                        const int* __restrict__ ptr,
                        const int* __restrict__ tni,
                        int E, int G) {
    int nE4 = E >> 2;
    int item = blockIdx.x * blockDim.x + threadIdx.x;
    if (item < nE4) {
        int4 s4 = __ldg((const int4*)ei + item);
        int4 d4 = __ldg((const int4*)(ei + E) + item);
        int p0 = __ldg(&ptr[0]);
        int stride = __ldg(&ptr[1]) - p0;
        #pragma unroll
        for (int q = 0; q < 4; q++) {
            int src = (q == 0) ? s4.x : (q == 1) ? s4.y : (q == 2) ? s4.z : s4.w;
            int dst = (q == 0) ? d4.x : (q == 1) ? d4.y : (q == 2) ? d4.z : d4.w;
            int g = -1;
            if (stride > 0) {
                int gg = (dst - p0) / stride;
                if (gg >= 0 && gg < G &&
                    __ldg(&ptr[gg]) <= dst && dst < __ldg(&ptr[gg + 1]))
                    g = gg;
            }
            if (g < 0) {  // non-uniform ptr fallback: binary search
                int lo = 0, hi = G;
                if (dst >= p0 && dst < __ldg(&ptr[G])) {
                    while (hi - lo > 1) {
                        int mid = (lo + hi) >> 1;
                        if (__ldg(&ptr[mid]) <= dst) lo = mid; else hi = mid;
                    }
                    g = lo;
                }
            }
            if (g >= 0 && __ldg(&ptr[g]) + __ldg(&tni[g]) == dst) {
                int pos = atomicAdd(&g_deg[g], 1);
                if (pos < CAP) g_ce_src[g * CAP + pos] = src;
            }
        }
    } else if (item - nE4 < G) {
        int g = item - nE4;                 // self loop of the target node
        int node = g_tgt_node[g];
        int pos = atomicAdd(&g_deg[g], 1);
        if (pos < CAP) g_ce_src[g * CAP + pos] = node;
    }
}

// ---------------- K3: fused logits + softmax + aggregation (x rows cached) ---
__global__ __launch_bounds__(256)
void k_agg(const float* __restrict__ x) {
    int t = blockIdx.x;
    int tid = threadIdx.x;                       // 256 = 8 warps
    int w = tid >> 5, lane = tid & 31;
    __shared__ __align__(16) float s_x[XCAP][F_IN];   // 32 KB row cache
    __shared__ int   s_src[CAP];
    __shared__ float s_v[CAP][HEADS];            // a_src, then alpha
    __shared__ __align__(16) float s_adst[HEADS];
    __shared__ float s_max[HEADS], s_sum[HEADS];

    int deg = min(g_deg[t], CAP);
    int tnode = g_tgt_node[t];

    for (int e = tid; e < deg; e += 256)
        s_src[e] = g_ce_src[t * CAP + e];
    __syncthreads();

    // warp 0 extra: target's a_dst
    if (w == 0) {
        float4 xv = __ldg((const float4*)(x + (size_t)tnode * F_IN) + lane);
        float d[HEADS];
        #pragma unroll
        for (int h = 0; h < HEADS; h++) {
            float4 wd = *((const float4*)&g_wdst[h][0] + lane);
            d[h] = xv.x * wd.x + xv.y * wd.y + xv.z * wd.z + xv.w * wd.w;
        }
        #pragma unroll
        for (int o = 16; o > 0; o >>= 1)
            #pragma unroll
            for (int h = 0; h < HEADS; h++)
                d[h] += __shfl_xor_sync(0xFFFFFFFFu, d[h], o);
        if (lane == 0)
            *(float4*)s_adst = make_float4(d[0], d[1], d[2], d[3]);
    }
    // all warps: per-edge a_src, 2 edges per warp per round; cache rows in smem
    for (int eb = w * 2; eb < deg; eb += 16) {
        int e1ok = (eb + 1 < deg);
        int src0 = s_src[eb];
        int src1 = e1ok ? s_src[eb + 1] : src0;
        float4 xv0 = __ldg((const float4*)(x + (size_t)src0 * F_IN) + lane);
        float4 xv1 = __ldg((const float4*)(x + (size_t)src1 * F_IN) + lane);
        if (eb < XCAP)
            *((float4*)&s_x[eb][0] + lane) = xv0;
        if (e1ok && eb + 1 < XCAP)
            *((float4*)&s_x[eb + 1][0] + lane) = xv1;
        float s0[HEADS], s1[HEADS];
        #pragma unroll
        for (int h = 0; h < HEADS; h++) {
            float4 ws = *((const float4*)&g_wsrc[h][0] + lane);
            s0[h] = xv0.x * ws.x + xv0.y * ws.y + xv0.z * ws.z + xv0.w * ws.w;
            s1[h] = xv1.x * ws.x + xv1.y * ws.y + xv1.z * ws.z + xv1.w * ws.w;
        }
        #pragma unroll
        for (int o = 16; o > 0; o >>= 1)
            #pragma unroll
            for (int h = 0; h < HEADS; h++) {
                s0[h] += __shfl_xor_sync(0xFFFFFFFFu, s0[h], o);
                s1[h] += __shfl_xor_sync(0xFFFFFFFFu, s1[h], o);
            }
        if (lane == 0) {
            *(float4*)&s_v[eb][0] = make_float4(s0[0], s0[1], s0[2], s0[3]);
            if (e1ok)
                *(float4*)&s_v[eb + 1][0] = make_float4(s1[0], s1[1], s1[2], s1[3]);
        }
    }
    __syncthreads();

    // per-head max + sum of exp (one warp per head)
    if (tid < 128) {
        int h = tid >> 5, l = tid & 31;
        float ad = s_adst[h];
        float m = -INFINITY;
        for (int e = l; e < deg; e += 32) {
            float v = s_v[e][h] + ad;
            v = (v > 0.f) ? v : NEG_SLOPE * v;
            m = fmaxf(m, v);
        }
        #pragma unroll
        for (int o = 16; o > 0; o >>= 1)
            m = fmaxf(m, __shfl_xor_sync(0xFFFFFFFFu, m, o));
        float sm = 0.f;
        for (int e = l; e < deg; e += 32) {
            float v = s_v[e][h] + ad;
            v = (v > 0.f) ? v : NEG_SLOPE * v;
            sm += expf(v - m);
        }
        #pragma unroll
        for (int o = 16; o > 0; o >>= 1)
            sm += __shfl_xor_sync(0xFFFFFFFFu, sm, o);
        if (l == 0) { s_max[h] = m; s_sum[h] = sm; }
    }
    __syncthreads();

    // alpha in place
    for (int e = tid; e < deg; e += 256) {
        #pragma unroll
        for (int h = 0; h < HEADS; h++) {
            float v = s_v[e][h] + s_adst[h];
            v = (v > 0.f) ? v : NEG_SLOPE * v;
            s_v[e][h] = expf(v - s_max[h]) / (s_sum[h] + 1e-16f);
        }
    }
    __syncthreads();

    // y[h][k] = sum_e alpha[e][h] * x_row[e][k]  (rows from smem cache)
    int k = tid & 127, hp = tid >> 7;            // hp: heads {0,1} or {2,3}
    int h0 = hp * 2, h1 = h0 + 1;
    float a0 = 0.f, a1 = 0.f;
    int e = 0;
    int dcap = min(deg, XCAP);
    for (; e + 2 <= dcap; e += 2) {
        float xv0 = s_x[e][k];
        float xv1 = s_x[e + 1][k];
        a0 += s_v[e][h0] * xv0 + s_v[e + 1][h0] * xv1;
        a1 += s_v[e][h1] * xv0 + s_v[e + 1][h1] * xv1;
    }
    for (; e < dcap; e++) {
        float xv = s_x[e][k];
        a0 += s_v[e][h0] * xv;
        a1 += s_v[e][h1] * xv;
    }
    for (; e < deg; e++) {   // overflow fallback (rare)
        float xv = __ldg(&x[(size_t)s_src[e] * F_IN + k]);
        a0 += s_v[e][h0] * xv;
        a1 += s_v[e][h1] * xv;
    }
    g_y[t][h0][k] = a0;
    g_y[t][h1][k] = a1;
}

// ---------------- K4: out = Y @ M + b2  ---------------------------------------
// grid = 2 * ceil(G/TB); blockIdx&1 selects 64-col half. 256 threads:
// jloc = tid&63 (column), ksub = tid>>6 (k-quarter of 512).
__global__ __launch_bounds__(256)
void k_out2(float* __restrict__ out, int G) {
    __shared__ __align__(16) float s_y[TB][YDIM];     // 32 KB
    __shared__ float s_part[4][TB][64];               // 16 KB

    int bc = blockIdx.x & 1;
    int t0 = (blockIdx.x >> 1) * TB;
    if (t0 >= G) return;
    int cnt = min(TB, G - t0);
    int tid = threadIdx.x;

    const float4* ysrc = (const float4*)&g_y[t0][0][0];
    float4* ydst = (float4*)&s_y[0][0];
    for (int i = tid; i < cnt * (YDIM / 4); i += 256)
        ydst[i] = ysrc[i];
    __syncthreads();

    int jloc = tid & 63, ksub = tid >> 6;
    int j = bc * 64 + jloc;
    int k0 = ksub * 128;

    float r[TB];
    #pragma unroll
    for (int t = 0; t < TB; t++) r[t] = 0.f;

    #pragma unroll 2
    for (int kk = 0; kk < 128; kk += 4) {
        int k = k0 + kk;
        float m0 = __ldg(&g_M[k + 0][j]);
        float m1 = __ldg(&g_M[k + 1][j]);
        float m2 = __ldg(&g_M[k + 2][j]);
        float m3 = __ldg(&g_M[k + 3][j]);
        #pragma unroll
        for (int t = 0; t < TB; t++) {
            float4 yv = *(const float4*)&s_y[t][k];
            r[t] += yv.x * m0 + yv.y * m1 + yv.z * m2 + yv.w * m3;
        }
    }
    #pragma unroll
    for (int t = 0; t < TB; t++) s_part[ksub][t][jloc] = r[t];
    __syncthreads();

    for (int idx = tid; idx < cnt * 64; idx += 256) {
        int t = idx >> 6, jl = idx & 63;
        float v = s_part[0][t][jl] + s_part[1][t][jl] +
                  s_part[2][t][jl] + s_part[3][t][jl];
        out[(size_t)(t0 + t) * HIDDEN + bc * 64 + jl] = v + g_b2[bc * 64 + jl];
    }
}

// ---------------- launch ----------------
extern "C" void kernel_launch(void* const* d_in, const int* in_sizes, int n_in,
                              void* d_out, int out_size) {
    const float* x        = (const float*)d_in[0];
    const float* W        = (const float*)d_in[1];
    const float* att_src  = (const float*)d_in[2];
    const float* att_dst  = (const float*)d_in[3];
    const float* bias     = (const float*)d_in[4];
    const float* fc_W     = (const float*)d_in[5];
    const float* fc_b     = (const float*)d_in[6];
    const int*   ei       = (const int*)d_in[7];
    const int*   ptr      = (const int*)d_in[8];
    const int*   tni      = (const int*)d_in[9];
    float*       out      = (float*)d_out;

    int E = in_sizes[7] / 2;           // 800000
    int G = in_sizes[9];               // 1000

    int TGB = (G + 255) / 256;
    k_setup<<<1 + TGB + 256 + 1, 256>>>(W, att_src, att_dst, fc_W, bias, fc_b,
                                        ptr, tni, G, TGB);
    int items = (E >> 2) + G;
    k_edges<<<(items + 255) / 256, 256>>>(ei, ptr, tni, E, G);
    k_agg<<<G, 256>>>(x);
    k_out2<<<2 * ((G + TB - 1) / TB), 256>>>(out, G);
}